// round 1
// baseline (speedup 1.0000x reference)
#include <cuda_runtime.h>
#include <cuda_bf16.h>
#include <cstdint>

// Problem constants (fixed by the dataset)
#define NB 10000     // base mesh vertices
#define MB_ 500000   // target vertices
#define BB 128       // batch of scalar fields

// Transposed f: fT[i*128 + b] = f[b*N + i]. 5.12 MB static device scratch.
__device__ float g_fT[NB * BB];

// ---------------------------------------------------------------------------
// Kernel A: tiled transpose f (B, N) -> fT (N, B)
// ---------------------------------------------------------------------------
__global__ void transpose_f_kernel(const float* __restrict__ f) {
    __shared__ float tile[32][33];
    const int i0 = blockIdx.x * 32;   // n-range
    const int b0 = blockIdx.y * 32;   // b-range
    const int tx = threadIdx.x;
    const int ty = threadIdx.y;

    // Read coalesced along n
    const int i = i0 + tx;
    if (i < NB) {
        tile[ty][tx] = f[(b0 + ty) * NB + i];   // holds (b=b0+ty, n=i0+tx)
    }
    __syncthreads();

    // Write coalesced along b
    const int iw = i0 + ty;
    if (iw < NB) {
        g_fT[iw * BB + (b0 + tx)] = tile[tx][ty];
    }
}

// ---------------------------------------------------------------------------
// Kernel B: barycentric interpolation via coalesced column gathers.
//
// Block = 256 threads (8 warps), m-tile = 64 per block.
//   warp w: m-subtile mt = (w/4)*32, b-range boff = (w%4)*32, lane = b offset.
//   Each lane accumulates acc[j] = out value at (b = boff+lane, m = m0+mt+j).
//   Column loads g_fT[idx*128 + boff + lane] are 128B coalesced, uniform idx.
//   Per-warp 32x33 padded smem transpose -> coalesced 128B row stores.
// ---------------------------------------------------------------------------
__global__ __launch_bounds__(256)
void bary_interp_kernel(const int*   __restrict__ tri_idx,
                        const float* __restrict__ bary_w,
                        float*       __restrict__ out) {
    __shared__ float s_tp[8][32][33];   // per-warp transpose tile (33.8 KB)
    __shared__ int   s_idx[64 * 3];
    __shared__ float s_w[64 * 3];

    const int tid  = threadIdx.x;
    const int w    = tid >> 5;
    const int lane = tid & 31;
    const int m0   = blockIdx.x * 64;

    // Cooperatively stage this block's indices/weights (zero-fill past M)
    for (int k = tid; k < 64 * 3; k += 256) {
        const long g = (long)m0 * 3 + k;
        if (g < (long)MB_ * 3) {
            s_idx[k] = tri_idx[g];
            s_w[k]   = bary_w[g];
        } else {
            s_idx[k] = 0;
            s_w[k]   = 0.0f;
        }
    }
    __syncthreads();

    const int mt   = (w >> 2) * 32;       // 0 or 32
    const int boff = (w & 3) * 32;        // 0, 32, 64, 96
    const int bl   = boff + lane;

    float acc[32];

    #pragma unroll
    for (int j = 0; j < 32; j++) {
        const int ml = mt + j;
        const int i0 = s_idx[ml * 3 + 0];
        const int i1 = s_idx[ml * 3 + 1];
        const int i2 = s_idx[ml * 3 + 2];
        const float w0 = s_w[ml * 3 + 0];
        const float w1 = s_w[ml * 3 + 1];
        const float w2 = s_w[ml * 3 + 2];

        const float a = __ldg(&g_fT[i0 * BB + bl]);
        const float b = __ldg(&g_fT[i1 * BB + bl]);
        const float c = __ldg(&g_fT[i2 * BB + bl]);

        acc[j] = w0 * a + w1 * b + w2 * c;
    }

    // Transpose within the warp's private tile: write lane-major (stride 33,
    // conflict-free), read m-major (stride 1, conflict-free).
    #pragma unroll
    for (int j = 0; j < 32; j++) {
        s_tp[w][lane][j] = acc[j];
    }
    __syncwarp();

    // Coalesced stores: lane indexes m, loop over the warp's 32 b-rows.
    const int mg = m0 + mt + lane;
    if (mg < MB_) {
        #pragma unroll 8
        for (int brow = 0; brow < 32; brow++) {
            out[(long)(boff + brow) * MB_ + mg] = s_tp[w][brow][lane];
        }
    }
}

// ---------------------------------------------------------------------------
// Launch
// ---------------------------------------------------------------------------
extern "C" void kernel_launch(void* const* d_in, const int* in_sizes, int n_in,
                              void* d_out, int out_size) {
    const float* f   = (const float*)d_in[0];   // (128, 10000) f32
    const int*   tri = (const int*)  d_in[1];   // (500000, 3) i32
    const float* bw  = (const float*)d_in[2];   // (500000, 3) f32
    float* out = (float*)d_out;                  // (128, 500000) f32

    // Kernel A: transpose f into g_fT
    {
        dim3 block(32, 32);
        dim3 grid((NB + 31) / 32, BB / 32);
        transpose_f_kernel<<<grid, block>>>(f);
    }

    // Kernel B: interpolation
    {
        const int nblocks = (MB_ + 63) / 64;   // 7813
        bary_interp_kernel<<<nblocks, 256>>>(tri, bw, out);
    }
}

// round 3
// speedup vs baseline: 1.1841x; 1.1841x over previous
#include <cuda_runtime.h>
#include <cuda_fp16.h>
#include <cstdint>

// Problem constants (fixed by the dataset)
#define NB 10000     // base mesh vertices
#define MB_ 500000   // target vertices
#define BB 128       // batch of scalar fields

// Transposed + fp16-staged f: g_fT_h[i*128 + b] = (half)f[b*N + i]. 2.56 MB.
__device__ __align__(16) __half g_fT_h[NB * BB];

// ---------------------------------------------------------------------------
// Kernel A: tiled transpose f (B, N) fp32 -> fT (N, B) fp16
// ---------------------------------------------------------------------------
__global__ void transpose_f_kernel(const float* __restrict__ f) {
    __shared__ float tile[32][33];
    const int i0 = blockIdx.x * 32;   // n-range
    const int b0 = blockIdx.y * 32;   // b-range
    const int tx = threadIdx.x;
    const int ty = threadIdx.y;

    const int i = i0 + tx;
    if (i < NB) {
        tile[ty][tx] = f[(b0 + ty) * NB + i];   // (b=b0+ty, n=i0+tx)
    }
    __syncthreads();

    const int iw = i0 + ty;
    if (iw < NB) {
        g_fT_h[iw * BB + (b0 + tx)] = __float2half_rn(tile[tx][ty]);
    }
}

// ---------------------------------------------------------------------------
// Kernel B: barycentric interpolation, fp16 column gathers (half2 per lane).
//
// Block = 256 threads (8 warps), tile = 64 m x 128 b.
//   warp w: b-half bh = w&1 (64 b-values), m-subtile mt = (w>>1)*16.
//   lane covers the b-pair (bh*64 + 2*lane, +1) via one __half2 load:
//   a warp's gather = 32 lanes x 4B = one fully packed 128B wavefront
//   covering 64 b-values for a single vertex index.
//   acc is float2[16] (fp32 accumulation).
//
//   Transpose via float2 smem tile s_out[b_pair][m] (pitch 65 -> conflict-free
//   STS.64 / LDS.64), then two coalesced 128B fp32 STG rows per read.
// ---------------------------------------------------------------------------
__global__ __launch_bounds__(256)
void bary_interp_kernel(const int*   __restrict__ tri_idx,
                        const float* __restrict__ bary_w,
                        float*       __restrict__ out) {
    __shared__ float2 s_out[64][65];    // 33.3 KB: [b-pair row][m col]
    __shared__ int    s_idx[64 * 3];
    __shared__ float  s_w[64 * 3];

    const int tid  = threadIdx.x;
    const int w    = tid >> 5;
    const int lane = tid & 31;
    const int m0   = blockIdx.x * 64;

    // Stage this block's indices/weights (zero-fill past M)
    for (int k = tid; k < 64 * 3; k += 256) {
        const long g = (long)m0 * 3 + k;
        if (g < (long)MB_ * 3) {
            s_idx[k] = tri_idx[g];
            s_w[k]   = bary_w[g];
        } else {
            s_idx[k] = 0;
            s_w[k]   = 0.0f;
        }
    }
    __syncthreads();

    const int bh  = (w & 1);            // which 64-wide b half
    const int mt  = (w >> 1) * 16;      // m subtile base
    const int col = bh * 32 + lane;     // half2 column index within a row
    const __half2* __restrict__ fT2 = (const __half2*)g_fT_h;  // row stride 64

    float2 acc[16];

    #pragma unroll
    for (int j = 0; j < 16; j++) {
        const int ml = mt + j;
        const int i0 = s_idx[ml * 3 + 0];
        const int i1 = s_idx[ml * 3 + 1];
        const int i2 = s_idx[ml * 3 + 2];
        const float w0 = s_w[ml * 3 + 0];
        const float w1 = s_w[ml * 3 + 1];
        const float w2 = s_w[ml * 3 + 2];

        const float2 a = __half22float2(fT2[i0 * 64 + col]);
        const float2 b = __half22float2(fT2[i1 * 64 + col]);
        const float2 c = __half22float2(fT2[i2 * 64 + col]);

        float2 r;
        r.x = fmaf(w0, a.x, fmaf(w1, b.x, w2 * c.x));
        r.y = fmaf(w0, a.y, fmaf(w1, b.y, w2 * c.y));
        acc[j] = r;
    }

    // Transpose tile write: row = b-pair index (bh*32+lane), col = m.
    // addr8 mod 16 = (65*lane + c) mod 16 = (lane + c) mod 16 -> conflict-free.
    #pragma unroll
    for (int j = 0; j < 16; j++) {
        s_out[col][mt + j] = acc[j];
    }
    __syncthreads();

    // Store: 64 b-pair rows x 2 m-halves = 128 tasks across 8 warps.
    // Each LDS.64 yields values for two adjacent b rows at m = lane
    // -> two coalesced 128B STG rows.
    for (int t = w; t < 128; t += 8) {
        const int b2 = t >> 1;
        const int mh = t & 1;
        const int mg = m0 + mh * 32 + lane;
        if (mg < MB_) {
            const float2 v = s_out[b2][mh * 32 + lane];
            out[(long)(2 * b2)     * MB_ + mg] = v.x;
            out[(long)(2 * b2 + 1) * MB_ + mg] = v.y;
        }
    }
}

// ---------------------------------------------------------------------------
// Launch
// ---------------------------------------------------------------------------
extern "C" void kernel_launch(void* const* d_in, const int* in_sizes, int n_in,
                              void* d_out, int out_size) {
    const float* f   = (const float*)d_in[0];   // (128, 10000) f32
    const int*   tri = (const int*)  d_in[1];   // (500000, 3) i32
    const float* bw  = (const float*)d_in[2];   // (500000, 3) f32
    float* out = (float*)d_out;                  // (128, 500000) f32

    // Kernel A: transpose + fp16 convert f into g_fT_h
    {
        dim3 block(32, 32);
        dim3 grid((NB + 31) / 32, BB / 32);
        transpose_f_kernel<<<grid, block>>>(f);
    }

    // Kernel B: interpolation
    {
        const int nblocks = (MB_ + 63) / 64;   // 7813
        bary_interp_kernel<<<nblocks, 256>>>(tri, bw, out);
    }
}

// round 5
// speedup vs baseline: 1.2355x; 1.0434x over previous
#include <cuda_runtime.h>
#include <cuda_fp16.h>
#include <cstdint>

// Problem constants (fixed by the dataset)
#define NB 10000     // base mesh vertices
#define MB_ 500000   // target vertices  (divisible by 32)
#define BB 128       // batch of scalar fields

// Transposed + fp16-staged f: g_fT_h[i*128 + b] = (half)f[b*N + i]. 2.56 MB.
__device__ __align__(16) __half g_fT_h[NB * BB];

// ---------------------------------------------------------------------------
// Kernel A: tiled transpose f (B, N) fp32 -> fT (N, B) fp16
// ---------------------------------------------------------------------------
__global__ void transpose_f_kernel(const float* __restrict__ f) {
    __shared__ float tile[32][33];
    const int i0 = blockIdx.x * 32;   // n-range
    const int b0 = blockIdx.y * 32;   // b-range
    const int tx = threadIdx.x;
    const int ty = threadIdx.y;

    const int i = i0 + tx;
    if (i < NB) {
        tile[ty][tx] = f[(b0 + ty) * NB + i];   // (b=b0+ty, n=i0+tx)
    }
    __syncthreads();

    const int iw = i0 + ty;
    if (iw < NB) {
        g_fT_h[iw * BB + (b0 + tx)] = __float2half_rn(tile[tx][ty]);
    }
}

// ---------------------------------------------------------------------------
// Kernel B: barycentric interpolation, fp16 column gathers (half2 per lane).
//
// Block = 256 threads (8 warps), tile = 32 m x 128 b.  (Tile halved vs R2
// to cut acc regs 32 -> 16 and lift occupancy 3 -> 5 blocks/SM.)
//   warp w: b-half bh = w&1 (64 b-values), m-subtile mt = (w>>1)*8.
//   lane covers b-pair (bh*64 + 2*lane, +1) via one __half2 load: a warp's
//   gather = one fully packed 128B wavefront covering 64 b for one vertex.
//   acc float2[8], fp32 accumulation.
//
//   Transpose via float2 smem tile s_out[b_pair][m] (pitch 33 -> conflict-free
//   STS.64/LDS.64), then two coalesced 128B fp32 STG rows per read.
// ---------------------------------------------------------------------------
__global__ __launch_bounds__(256, 5)
void bary_interp_kernel(const int*   __restrict__ tri_idx,
                        const float* __restrict__ bary_w,
                        float*       __restrict__ out) {
    __shared__ float2 s_out[64][33];    // 16.9 KB: [b-pair row][m col]
    __shared__ int    s_idx[32 * 3];
    __shared__ float  s_w[32 * 3];

    const int tid  = threadIdx.x;
    const int w    = tid >> 5;
    const int lane = tid & 31;
    const int m0   = blockIdx.x * 32;

    // Stage this block's indices/weights (M divisible by 32 -> no guards)
    if (tid < 96) {
        const long g = (long)m0 * 3 + tid;
        s_idx[tid] = tri_idx[g];
        s_w[tid]   = bary_w[g];
    }
    __syncthreads();

    const int bh  = (w & 1);            // which 64-wide b half
    const int mt  = (w >> 1) * 8;       // m subtile base
    const int col = bh * 32 + lane;     // half2 column index within a row
    const __half2* __restrict__ fT2 = (const __half2*)g_fT_h;  // row stride 64

    float2 acc[8];

    #pragma unroll
    for (int j = 0; j < 8; j++) {
        const int ml = mt + j;
        const int i0 = s_idx[ml * 3 + 0];
        const int i1 = s_idx[ml * 3 + 1];
        const int i2 = s_idx[ml * 3 + 2];
        const float w0 = s_w[ml * 3 + 0];
        const float w1 = s_w[ml * 3 + 1];
        const float w2 = s_w[ml * 3 + 2];

        const float2 a = __half22float2(fT2[i0 * 64 + col]);
        const float2 b = __half22float2(fT2[i1 * 64 + col]);
        const float2 c = __half22float2(fT2[i2 * 64 + col]);

        float2 r;
        r.x = fmaf(w0, a.x, fmaf(w1, b.x, w2 * c.x));
        r.y = fmaf(w0, a.y, fmaf(w1, b.y, w2 * c.y));
        acc[j] = r;
    }

    // Transpose tile write: row = b-pair index (bh*32+lane), col = m.
    // addr8 mod 16 = (33*lane + c) mod 16 = (lane + c) mod 16 -> conflict-free.
    #pragma unroll
    for (int j = 0; j < 8; j++) {
        s_out[col][mt + j] = acc[j];
    }
    __syncthreads();

    // Store: 64 b-pair rows across 8 warps, 8 rows each.
    // Each LDS.64 yields two adjacent b rows at m = lane -> two coalesced
    // 128B STG rows.
    #pragma unroll
    for (int t = 0; t < 8; t++) {
        const int b2 = w * 8 + t;
        const int mg = m0 + lane;
        const float2 v = s_out[b2][lane];
        out[(long)(2 * b2)     * MB_ + mg] = v.x;
        out[(long)(2 * b2 + 1) * MB_ + mg] = v.y;
    }
}

// ---------------------------------------------------------------------------
// Launch
// ---------------------------------------------------------------------------
extern "C" void kernel_launch(void* const* d_in, const int* in_sizes, int n_in,
                              void* d_out, int out_size) {
    const float* f   = (const float*)d_in[0];   // (128, 10000) f32
    const int*   tri = (const int*)  d_in[1];   // (500000, 3) i32
    const float* bw  = (const float*)d_in[2];   // (500000, 3) f32
    float* out = (float*)d_out;                  // (128, 500000) f32

    // Kernel A: transpose + fp16 convert f into g_fT_h
    {
        dim3 block(32, 32);
        dim3 grid((NB + 31) / 32, BB / 32);
        transpose_f_kernel<<<grid, block>>>(f);
    }

    // Kernel B: interpolation
    {
        const int nblocks = MB_ / 32;   // 15625
        bary_interp_kernel<<<nblocks, 256>>>(tri, bw, out);
    }
}